// round 1
// baseline (speedup 1.0000x reference)
#include <cuda_runtime.h>
#include <cuda_bf16.h>

#define N_GT     32
#define MAX_AC   2304          // 16*16*9 upper bound before boundary filtering
#define KMAX     9             // ceil(MAX_AC / THREADS)
#define THREADS  256

__global__ __launch_bounds__(THREADS) void rpn_kernel(
    const float4* __restrict__ bx_gt,    // [B, 32] float4
    const float4* __restrict__ ac_val,   // [n_ac] float4
    const float*  __restrict__ rand_pos, // [B, n_ac]
    const float*  __restrict__ rand_neg, // [B, n_ac]
    float* __restrict__ out,             // [B, n_ac, 10]
    int n_ac)
{
    const int b    = blockIdx.x;
    const int tid  = threadIdx.x;
    const int lane = tid & 31;

    __shared__ float4   gts[N_GT];
    __shared__ float    gt_area[N_GT];
    __shared__ int      gtmax[N_GT];          // packed (iou<<12)|(4095-ac)
    __shared__ int      acinfo[MAX_AC];       // packed (iou<<5)|best_gt
    __shared__ unsigned posbm[MAX_AC / 32];
    __shared__ int      cpos, cneg;

    // ---- Phase 0: load GT boxes / init ----
    if (tid < N_GT) {
        float4 g = bx_gt[b * N_GT + tid];
        gts[tid] = g;
        gt_area[tid] = __fmul_rn(__fsub_rn(g.z, g.x), __fsub_rn(g.w, g.y));
        gtmax[tid] = -1;
    }
    for (int i = tid; i < MAX_AC / 32; i += THREADS) posbm[i] = 0u;
    if (tid == 0) { cpos = 0; cneg = 0; }
    __syncthreads();

    // ---- cache this thread's anchors in registers ----
    float4 A[KMAX];
    float  AR[KMAX];
    #pragma unroll
    for (int k = 0; k < KMAX; k++) {
        int a = tid + k * THREADS;
        if (a < n_ac) {
            float4 v = ac_val[a];
            A[k]  = v;
            AR[k] = __fmul_rn(__fsub_rn(v.z, v.x), __fsub_rn(v.w, v.y));
        }
    }

    int bi[KMAX], bg[KMAX];
    #pragma unroll
    for (int k = 0; k < KMAX; k++) { bi[k] = -1; bg[k] = 0; }

    // ---- Phase 1: IOU matrix + bidirectional argmax ----
    for (int g = 0; g < N_GT; g++) {
        float4 G  = gts[g];
        float  GA = gt_area[g];
        int gml = -1;
        #pragma unroll
        for (int k = 0; k < KMAX; k++) {
            int a = tid + k * THREADS;
            if (a < n_ac) {
                // bit-exact fp32 (no FMA contraction) to match the reference's
                // int32 truncation of iou*10000
                float ih = fmaxf(__fsub_rn(fminf(A[k].z, G.z), fmaxf(A[k].x, G.x)), 0.0f);
                float iw = fmaxf(__fsub_rn(fminf(A[k].w, G.w), fmaxf(A[k].y, G.y)), 0.0f);
                float inter = __fmul_rn(ih, iw);
                float uni   = __fsub_rn(__fadd_rn(AR[k], GA), inter);
                float iou   = __fdiv_rn(inter, __fadd_rn(uni, 1e-5f));
                int   ii    = (int)__fmul_rn(iou, 10000.0f);  // trunc toward 0, same as astype(int32)
                if (ii > bi[k]) { bi[k] = ii; bg[k] = g; }    // first-index argmax over gt
                gml = max(gml, (ii << 12) | (4095 - a));      // smallest anchor wins ties
            }
        }
        int v = __reduce_max_sync(0xffffffffu, gml);
        if (lane == 0) atomicMax(&gtmax[g], v);
    }
    #pragma unroll
    for (int k = 0; k < KMAX; k++) {
        int a = tid + k * THREADS;
        if (a < n_ac) acinfo[a] = (bi[k] << 5) | bg[k];
    }
    __syncthreads();

    // ---- Phase 2: scatter gt->anchor positives (POS_TH_GTAC = 100) ----
    if (tid < N_GT) {
        int p = gtmax[tid];
        int iou_gtac = p >> 12;
        if (iou_gtac >= 100) {
            int a = 4095 - (p & 4095);
            atomicOr(&posbm[a >> 5], 1u << (a & 31));
        }
    }
    __syncthreads();

    // ---- Phase 3: count pos / neg for sampling thresholds ----
    int lp = 0, ln = 0;
    #pragma unroll
    for (int k = 0; k < KMAX; k++) {
        int a = tid + k * THREADS;
        if (a < n_ac) {
            int  iou = acinfo[a] >> 5;
            bool pg  = (posbm[a >> 5] >> (a & 31)) & 1u;
            bool pos = (iou >= 5000) || pg;
            bool neg = (iou < 3000) && !pos;
            lp += pos ? 1 : 0;
            ln += neg ? 1 : 0;
        }
    }
    lp = __reduce_add_sync(0xffffffffu, lp);
    ln = __reduce_add_sync(0xffffffffu, ln);
    if (lane == 0) { atomicAdd(&cpos, lp); atomicAdd(&cneg, ln); }
    __syncthreads();

    float thp = __fdiv_rn(128.0f, __fadd_rn((float)cpos, 1e-6f));
    float thn = __fdiv_rn(128.0f, __fadd_rn((float)cneg, 1e-6f));

    const float* rp = rand_pos + (size_t)b * n_ac;
    const float* rn = rand_neg + (size_t)b * n_ac;
    float*       ob = out      + (size_t)b * n_ac * 10;

    // ---- Phase 4: emit [bx_tgt(4), bx_del(4), mask_pos, mask_neg] ----
    #pragma unroll
    for (int k = 0; k < KMAX; k++) {
        int a = tid + k * THREADS;
        if (a < n_ac) {
            int  info = acinfo[a];
            int  iou  = info >> 5;
            int  bgk  = info & 31;
            bool pg   = (posbm[a >> 5] >> (a & 31)) & 1u;
            bool pos  = (iou >= 5000) || pg;
            bool neg  = (iou < 3000) && !pos;

            float o0, o1, o2, o3, d0, d1, d2, d3;
            if (pos) {
                float4 G = gts[bgk];
                o0 = G.x; o1 = G.y; o2 = G.z; o3 = G.w;
                float4 ac = A[k];
                float hr  = fmaxf(ac.z - ac.x, 1e-5f);
                float wr  = fmaxf(ac.w - ac.y, 1e-5f);
                float ycr = ac.x + 0.5f * (ac.z - ac.x);
                float xcr = ac.y + 0.5f * (ac.w - ac.y);
                float hl  = G.z - G.x;
                float wl  = G.w - G.y;
                float ycl = G.x + 0.5f * hl;
                float xcl = G.y + 0.5f * wl;
                d0 = (xcl - xcr) / wr;
                d1 = (ycl - ycr) / hr;
                d2 = logf(wl / wr);
                d3 = logf(hl / hr);
                d0 = fminf(fmaxf(d0, -10.0f), 10.0f);
                d1 = fminf(fmaxf(d1, -10.0f), 10.0f);
                d2 = fminf(fmaxf(d2, -10.0f), 10.0f);
                d3 = fminf(fmaxf(d3, -10.0f), 10.0f);
            } else {
                // non-pos: bx_safe == anchor => delta is exactly 0
                float v = neg ? -2.0f : -1.0f;
                o0 = o1 = o2 = o3 = v;
                d0 = d1 = d2 = d3 = 0.0f;
            }
            // mask_fg == pos (gt coords sum >= 0 > -4), mask_bg == neg (sum = -8)
            float mp = (pos && (rp[a] < thp)) ? 1.0f : 0.0f;
            float mn = (neg && (rn[a] < thn)) ? 1.0f : 0.0f;

            float* op = ob + (size_t)a * 10;
            op[0] = o0; op[1] = o1; op[2] = o2; op[3] = o3;
            op[4] = d0; op[5] = d1; op[6] = d2; op[7] = d3;
            op[8] = mp; op[9] = mn;
        }
    }
}

extern "C" void kernel_launch(void* const* d_in, const int* in_sizes, int n_in,
                              void* d_out, int out_size) {
    const float4* bx_gt = (const float4*)d_in[0];
    const float4* ac    = (const float4*)d_in[1];
    const float*  rp    = (const float*)d_in[2];
    const float*  rn    = (const float*)d_in[3];
    float*        out   = (float*)d_out;

    int n_ac = in_sizes[1] / 4;
    int B    = in_sizes[0] / (N_GT * 4);

    rpn_kernel<<<B, THREADS>>>(bx_gt, ac, rp, rn, out, n_ac);
}

// round 2
// speedup vs baseline: 1.5123x; 1.5123x over previous
#include <cuda_runtime.h>

#define NGT   32
#define MAXB  1024
#define MAXA  3072
#define K1T   128   // K1 threads
#define K1K   3     // anchors per K1 thread
#define CHUNK (K1T*K1K)  // 384 anchors per K1 CTA

__device__ int g_gtmax[MAXB * NGT];     // packed (ii<<12)|(4095-a), atomicMax-combined
__device__ int g_acinfo[MAXB * MAXA];   // packed ii*32 + (31-best_gt), exclusive store

// ---------- K0: zero the gt->anchor max scratch ----------
__global__ void k0_init(int n) {
    int i = blockIdx.x * blockDim.x + threadIdx.x;
    if (i < n) g_gtmax[i] = 0;   // 0 decodes to ii=0 (<100 threshold) -> inert
}

// ---------- K1: IOU engine (one CTA = one batch x one 384-anchor chunk) ----------
__global__ __launch_bounds__(K1T) void k1_iou(
    const float4* __restrict__ bx_gt,   // [B,32]
    const float4* __restrict__ ac_val,  // [n_ac]
    int n_ac)
{
    const int b    = blockIdx.y;
    const int tid  = threadIdx.x;
    const int lane = tid & 31;
    const int base = blockIdx.x * CHUNK;

    __shared__ float4 gts[NGT];
    __shared__ float  gta[NGT];

    if (tid < NGT) {
        float4 g = bx_gt[b * NGT + tid];
        gts[tid] = g;
        gta[tid] = __fmul_rn(__fsub_rn(g.z, g.x), __fsub_rn(g.w, g.y));
    }

    // Registers: this thread's 3 anchors. Dead slots get a far-away dummy box:
    // inter is always 0 for it, and since its index exceeds every real index,
    // its packed candidates lose all ties. Provably inert.
    float4 A[K1K]; float AR[K1K]; int na[K1K]; int best[K1K];
    #pragma unroll
    for (int k = 0; k < K1K; k++) {
        int a = base + tid + k * K1T;
        if (a < n_ac) {
            float4 v = __ldg(&ac_val[a]);
            A[k]  = v;
            AR[k] = __fmul_rn(__fsub_rn(v.z, v.x), __fsub_rn(v.w, v.y));
        } else {
            A[k]  = make_float4(1e9f, 1e9f, 1e9f, 1e9f);
            AR[k] = 0.0f;
        }
        na[k]   = 4095 - a;   // a <= 3455 always, so na >= 0
        best[k] = 0;          // g=0 candidate is always >= 31, so init-0 never wins
    }
    __syncthreads();

    #pragma unroll 2
    for (int g = 0; g < NGT; g++) {
        float4 G  = gts[g];
        float  GA = gta[g];
        int    wg = 31 - g;   // larger = earlier gt -> first-index tie-break
        int    gml = 0;
        #pragma unroll
        for (int k = 0; k < K1K; k++) {
            // bit-exact fp32 (no FMA contraction): reference truncates iou*1e4 to int
            float ih    = fmaxf(__fsub_rn(fminf(A[k].z, G.z), fmaxf(A[k].x, G.x)), 0.0f);
            float iw    = fmaxf(__fsub_rn(fminf(A[k].w, G.w), fmaxf(A[k].y, G.y)), 0.0f);
            float inter = __fmul_rn(ih, iw);
            float uni   = __fsub_rn(__fadd_rn(AR[k], GA), inter);
            float iou   = __fdiv_rn(inter, __fadd_rn(uni, 1e-5f));
            int   ii    = (int)__fmul_rn(iou, 10000.0f);   // trunc == astype(int32)
            best[k] = max(best[k], ii * 32   + wg);        // ac->gt argmax (IMAD on fma pipe)
            gml     = max(gml,     ii * 4096 + na[k]);     // gt->ac argmax
        }
        int v = __reduce_max_sync(0xffffffffu, gml);
        if (lane == 0) atomicMax(&g_gtmax[b * NGT + g], v);
    }

    #pragma unroll
    for (int k = 0; k < K1K; k++) {
        int a = base + tid + k * K1T;
        if (a < n_ac) g_acinfo[b * MAXA + a] = best[k];
    }
}

// ---------- K2: posbm scatter + pos/neg counting + output emit ----------
__global__ __launch_bounds__(256) void k2_emit(
    const float4* __restrict__ bx_gt,
    const float4* __restrict__ ac_val,
    const float*  __restrict__ rand_pos,
    const float*  __restrict__ rand_neg,
    float* __restrict__ out,
    int n_ac)
{
    const int b    = blockIdx.x;
    const int tid  = threadIdx.x;
    const int lane = tid & 31;

    __shared__ float4   gts[NGT];
    __shared__ unsigned posbm[MAXA / 32];
    __shared__ int      cpos, cneg;

    if (tid < NGT) gts[tid] = bx_gt[b * NGT + tid];
    for (int i = tid; i < MAXA / 32; i += 256) posbm[i] = 0u;
    if (tid == 0) { cpos = 0; cneg = 0; }
    __syncthreads();

    // scatter gt->anchor positives (POS_TH_GTAC = 100)
    if (tid < NGT) {
        int p = g_gtmax[b * NGT + tid];
        if ((p >> 12) >= 100) {
            int a = 4095 - (p & 4095);
            atomicOr(&posbm[a >> 5], 1u << (a & 31));
        }
    }
    __syncthreads();

    // count pos / neg for sampling thresholds
    int lp = 0, ln = 0;
    for (int a = tid; a < n_ac; a += 256) {
        int  ii  = g_acinfo[b * MAXA + a] >> 5;
        bool pg  = (posbm[a >> 5] >> (a & 31)) & 1u;
        bool pos = (ii >= 5000) || pg;
        bool neg = (ii < 3000) && !pos;
        lp += pos ? 1 : 0;
        ln += neg ? 1 : 0;
    }
    lp = __reduce_add_sync(0xffffffffu, lp);
    ln = __reduce_add_sync(0xffffffffu, ln);
    if (lane == 0) { atomicAdd(&cpos, lp); atomicAdd(&cneg, ln); }
    __syncthreads();

    float thp = __fdiv_rn(128.0f, __fadd_rn((float)cpos, 1e-6f));
    float thn = __fdiv_rn(128.0f, __fadd_rn((float)cneg, 1e-6f));

    const float* rp = rand_pos + (size_t)b * n_ac;
    const float* rn = rand_neg + (size_t)b * n_ac;
    float*       ob = out      + (size_t)b * n_ac * 10;

    // emit [bx_tgt(4), bx_del(4), mask_pos, mask_neg] as 5x float2 stores
    for (int a = tid; a < n_ac; a += 256) {
        int  info = g_acinfo[b * MAXA + a];
        int  ii   = info >> 5;
        int  bg   = 31 - (info & 31);
        bool pg   = (posbm[a >> 5] >> (a & 31)) & 1u;
        bool pos  = (ii >= 5000) || pg;
        bool neg  = (ii < 3000) && !pos;

        float o0, o1, o2, o3, d0, d1, d2, d3;
        if (pos) {
            float4 G = gts[bg];
            o0 = G.x; o1 = G.y; o2 = G.z; o3 = G.w;
            float4 av = __ldg(&ac_val[a]);
            float hr  = fmaxf(av.z - av.x, 1e-5f);
            float wr  = fmaxf(av.w - av.y, 1e-5f);
            float ycr = av.x + 0.5f * (av.z - av.x);
            float xcr = av.y + 0.5f * (av.w - av.y);
            float hl  = G.z - G.x;
            float wl  = G.w - G.y;
            float ycl = G.x + 0.5f * hl;
            float xcl = G.y + 0.5f * wl;
            d0 = fminf(fmaxf((xcl - xcr) / wr, -10.0f), 10.0f);
            d1 = fminf(fmaxf((ycl - ycr) / hr, -10.0f), 10.0f);
            d2 = fminf(fmaxf(logf(wl / wr),   -10.0f), 10.0f);
            d3 = fminf(fmaxf(logf(hl / hr),   -10.0f), 10.0f);
        } else {
            // non-pos: bx_safe == anchor => delta is exactly 0
            float v = neg ? -2.0f : -1.0f;
            o0 = o1 = o2 = o3 = v;
            d0 = d1 = d2 = d3 = 0.0f;
        }
        float mp = (pos && (rp[a] < thp)) ? 1.0f : 0.0f;
        float mn = (neg && (rn[a] < thn)) ? 1.0f : 0.0f;

        float2* op = (float2*)(ob + (size_t)a * 10);   // 8-byte aligned (a*40)
        op[0] = make_float2(o0, o1);
        op[1] = make_float2(o2, o3);
        op[2] = make_float2(d0, d1);
        op[3] = make_float2(d2, d3);
        op[4] = make_float2(mp, mn);
    }
}

extern "C" void kernel_launch(void* const* d_in, const int* in_sizes, int n_in,
                              void* d_out, int out_size) {
    const float4* bx_gt = (const float4*)d_in[0];
    const float4* ac    = (const float4*)d_in[1];
    const float*  rp    = (const float*)d_in[2];
    const float*  rn    = (const float*)d_in[3];
    float*        out   = (float*)d_out;

    int n_ac  = in_sizes[1] / 4;
    int B     = in_sizes[0] / (NGT * 4);
    int split = (n_ac + CHUNK - 1) / CHUNK;

    k0_init<<<(B * NGT + 255) / 256, 256>>>(B * NGT);
    k1_iou<<<dim3(split, B), K1T>>>(bx_gt, ac, n_ac);
    k2_emit<<<B, 256>>>(bx_gt, ac, rp, rn, out, n_ac);
}